// round 8
// baseline (speedup 1.0000x reference)
#include <cuda_runtime.h>
#include <cuda_bf16.h>
#include <stdint.h>

// Problem constants (fixed by the dataset)
#define MAXN 100000
#define MAXE 1600000
#define DIM  256
#define DIM2 512

// ---------------- scratch (no allocations allowed) ----------------
__device__ float g_h0[(size_t)MAXN * DIM];    // (1+eps)*x + neigh
__device__ float g_h1[(size_t)MAXN * DIM2];   // after MLP layer 1 (relu)
__device__ int   g_counts[MAXN];
__device__ int   g_offsets[MAXN];
__device__ int   g_cursor[MAXN];
__device__ int   g_edge_src[MAXE];
__device__ int   g_blockSums[256];
__device__ float g_colSum[DIM];
__device__ float g_colSq[DIM];
__device__ float g_mean[DIM];
__device__ float g_rstd[DIM];
__device__ int   g_is64;        // 1 if src/dst are int64, 0 if int32

// ---------------- dtype probe ----------------
// For int64 data (values < 2^31), every odd 32-bit word is 0.
// For int32 data, odd words are random node ids — all-zero is impossible.
__global__ void detect_idx_kernel(const int* __restrict__ dst_i32, int* __restrict__ is64) {
    __shared__ int any_nonzero;
    if (threadIdx.x == 0) any_nonzero = 0;
    __syncthreads();
    int v = dst_i32[2 * threadIdx.x + 1];   // 64 odd words
    if (v != 0) atomicOr(&any_nonzero, 1);
    __syncthreads();
    if (threadIdx.x == 0) *is64 = (any_nonzero == 0) ? 1 : 0;
}

__device__ __forceinline__ int load_idx(const void* p, int i, int is64) {
    if (is64) return (int)((const long long*)p)[i];
    return ((const int*)p)[i];
}

// ---------------- small utility kernels ----------------
__global__ void zero_int2(int* a, int n, int* b, int m) {
    int i = blockIdx.x * blockDim.x + threadIdx.x;
    if (i < n) a[i] = 0;
    if (i < m) b[i] = 0;
}

__global__ void zero_f2(float* a, float* b, int n) {
    int i = blockIdx.x * blockDim.x + threadIdx.x;
    if (i < n) { a[i] = 0.f; b[i] = 0.f; }
}

// histogram of dst
__global__ void hist_kernel(const void* __restrict__ dst, int* __restrict__ counts, int E,
                            const int* __restrict__ is64p) {
    int i = blockIdx.x * blockDim.x + threadIdx.x;
    if (i < E) {
        int d = load_idx(dst, i, *is64p);
        atomicAdd(&counts[d], 1);
    }
}

// exclusive scan: per-chunk (1024) partial
__global__ void scan_partial(const int* __restrict__ counts, int* __restrict__ offsets,
                             int* __restrict__ blockSums, int n) {
    __shared__ int sh[1024];
    int t = threadIdx.x;
    int i = blockIdx.x * 1024 + t;
    int v = (i < n) ? counts[i] : 0;
    sh[t] = v;
    __syncthreads();
    for (int off = 1; off < 1024; off <<= 1) {
        int x = (t >= off) ? sh[t - off] : 0;
        __syncthreads();
        sh[t] += x;
        __syncthreads();
    }
    if (i < n) offsets[i] = sh[t] - v;          // exclusive within chunk
    if (t == 1023) blockSums[blockIdx.x] = sh[t];
}

__global__ void scan_root(int* blockSums, int nb) {
    if (threadIdx.x == 0 && blockIdx.x == 0) {
        int run = 0;
        for (int i = 0; i < nb; i++) { int v = blockSums[i]; blockSums[i] = run; run += v; }
    }
}

__global__ void scan_add(int* __restrict__ offsets, const int* __restrict__ blockSums, int n) {
    int i = blockIdx.x * 1024 + threadIdx.x;
    if (i < n) offsets[i] += blockSums[blockIdx.x];
}

// scatter edge sources into CSR buckets
__global__ void scatter_kernel(const void* __restrict__ src, const void* __restrict__ dst,
                               const int* __restrict__ offsets, int* __restrict__ cursor,
                               int* __restrict__ edge_src, int E,
                               const int* __restrict__ is64p) {
    int i = blockIdx.x * blockDim.x + threadIdx.x;
    if (i < E) {
        int is64 = *is64p;
        int d = load_idx(dst, i, is64);
        int s = load_idx(src, i, is64);
        int p = atomicAdd(&cursor[d], 1);
        edge_src[offsets[d] + p] = s;
    }
}

// per-node gather-sum: h0[v] = (1+eps)*x[v] + sum_{u in N(v)} x[u]
__global__ void aggregate_kernel(const float* __restrict__ nf,
                                 const int* __restrict__ offsets,
                                 const int* __restrict__ counts,
                                 const int* __restrict__ edge_src,
                                 const float* __restrict__ eps,
                                 float* __restrict__ h0, int n) {
    int v = blockIdx.x;
    if (v >= n) return;
    int t = threadIdx.x;                         // 64 threads, each one float4 (16 B) of the row
    float s = 1.0f + eps[0];
    float4 a = *(const float4*)(nf + (size_t)v * DIM + t * 4);
    float4 acc = make_float4(a.x * s, a.y * s, a.z * s, a.w * s);
    int off = offsets[v];
    int deg = counts[v];
    int j = 0;
    for (; j + 4 <= deg; j += 4) {               // batch 4 rows for MLP
        int u0 = edge_src[off + j + 0];
        int u1 = edge_src[off + j + 1];
        int u2 = edge_src[off + j + 2];
        int u3 = edge_src[off + j + 3];
        float4 b0 = *(const float4*)(nf + (size_t)u0 * DIM + t * 4);
        float4 b1 = *(const float4*)(nf + (size_t)u1 * DIM + t * 4);
        float4 b2 = *(const float4*)(nf + (size_t)u2 * DIM + t * 4);
        float4 b3 = *(const float4*)(nf + (size_t)u3 * DIM + t * 4);
        acc.x += b0.x + b1.x + b2.x + b3.x;
        acc.y += b0.y + b1.y + b2.y + b3.y;
        acc.z += b0.z + b1.z + b2.z + b3.z;
        acc.w += b0.w + b1.w + b2.w + b3.w;
    }
    for (; j < deg; j++) {
        int u = edge_src[off + j];
        float4 b = *(const float4*)(nf + (size_t)u * DIM + t * 4);
        acc.x += b.x; acc.y += b.y; acc.z += b.z; acc.w += b.w;
    }
    *(float4*)(h0 + (size_t)v * DIM + t * 4) = acc;
}

// ---------------- fp32 SIMT GEMM: C[M,N] = A[M,K] @ B[K,N] + bias, optional relu ----
// BM=128, BN=64, BK=16, 256 threads, 8x4 per thread, vectorized LDS
template <bool RELU>
__global__ void __launch_bounds__(256, 4)
gemm_kernel(const float* __restrict__ A, const float* __restrict__ B,
            const float* __restrict__ bias, float* __restrict__ C,
            int M, int N, int K) {
    __shared__ float As[16][136];   // [k][m], padded so rows are 16B-aligned (136*4=544=34*16)
    __shared__ float Bs[16][64];    // [k][n]

    const int tid = threadIdx.x;
    const int tx = tid & 15;   // col group 0..15  -> 4 cols each
    const int ty = tid >> 4;   // row group 0..15  -> 8 rows each
    const int row0 = blockIdx.y * 128;
    const int col0 = blockIdx.x * 64;

    float acc[8][4];
#pragma unroll
    for (int i = 0; i < 8; i++)
#pragma unroll
        for (int j = 0; j < 4; j++) acc[i][j] = 0.f;

    for (int k0 = 0; k0 < K; k0 += 16) {
        // A tile: 128x16 = 512 float4; 2 float4 per thread, transposed store
#pragma unroll
        for (int i = 0; i < 2; i++) {
            int id = tid * 2 + i;
            int r  = id >> 2;          // 0..127
            int c4 = id & 3;           // 0..3
            int gr = row0 + r;
            float4 v = make_float4(0.f, 0.f, 0.f, 0.f);
            if (gr < M) v = *(const float4*)(A + (size_t)gr * K + k0 + c4 * 4);
            As[c4 * 4 + 0][r] = v.x;
            As[c4 * 4 + 1][r] = v.y;
            As[c4 * 4 + 2][r] = v.z;
            As[c4 * 4 + 3][r] = v.w;
        }
        // B tile: 16x64 = 256 float4; 1 per thread
        {
            int r  = tid >> 4;   // 0..15
            int c4 = tid & 15;   // 0..15
            *(float4*)&Bs[r][c4 * 4] = *(const float4*)(B + (size_t)(k0 + r) * N + col0 + c4 * 4);
        }
        __syncthreads();

#pragma unroll
        for (int kk = 0; kk < 16; kk++) {
            // vectorized operand fetch: 2x LDS.128 for a, 1x LDS.128 for b
            float4 a01 = *(const float4*)&As[kk][ty * 8 + 0];
            float4 a23 = *(const float4*)&As[kk][ty * 8 + 4];
            float4 bv  = *(const float4*)&Bs[kk][tx * 4];
            float a[8] = {a01.x, a01.y, a01.z, a01.w, a23.x, a23.y, a23.z, a23.w};
            float b[4] = {bv.x, bv.y, bv.z, bv.w};
#pragma unroll
            for (int i = 0; i < 8; i++)
#pragma unroll
                for (int j = 0; j < 4; j++) acc[i][j] += a[i] * b[j];
        }
        __syncthreads();
    }

    // epilogue
#pragma unroll
    for (int i = 0; i < 8; i++) {
        int r = row0 + ty * 8 + i;
        if (r >= M) continue;
#pragma unroll
        for (int j = 0; j < 4; j++) {
            int c = col0 + tx * 4 + j;
            float v = acc[i][j] + bias[c];
            if (RELU) v = fmaxf(v, 0.f);
            C[(size_t)r * N + c] = v;
        }
    }
}

// ---------------- BatchNorm ----------------
__global__ void bn_stats(const float* __restrict__ h, int M,
                         float* __restrict__ colSum, float* __restrict__ colSq) {
    int c = threadIdx.x;   // 256 threads = one per column
    float s = 0.f, q = 0.f;
    for (int r = blockIdx.x; r < M; r += gridDim.x) {
        float v = h[(size_t)r * DIM + c];
        s += v;
        q += v * v;
    }
    atomicAdd(&colSum[c], s);
    atomicAdd(&colSq[c], q);
}

__global__ void bn_final(const float* __restrict__ colSum, const float* __restrict__ colSq,
                         float* __restrict__ mean, float* __restrict__ rstd, int M) {
    int c = threadIdx.x;
    float invM = 1.0f / (float)M;
    float m = colSum[c] * invM;
    float var = colSq[c] * invM - m * m;
    mean[c] = m;
    rstd[c] = rsqrtf(var + 1e-5f);
}

__global__ void bn_apply(float* __restrict__ h,
                         const float* __restrict__ mean, const float* __restrict__ rstd,
                         const float* __restrict__ gamma, const float* __restrict__ beta,
                         int nvec) {
    int i = blockIdx.x * blockDim.x + threadIdx.x;   // float4 index
    if (i >= nvec) return;
    int c4 = (i & 63) * 4;                           // column of first element
    float4 v = ((float4*)h)[i];
    float4 m = *(const float4*)(mean + c4);
    float4 r = *(const float4*)(rstd + c4);
    float4 g = *(const float4*)(gamma + c4);
    float4 b = *(const float4*)(beta + c4);
    v.x = (v.x - m.x) * r.x * g.x + b.x;
    v.y = (v.y - m.y) * r.y * g.y + b.y;
    v.z = (v.z - m.z) * r.z * g.z + b.z;
    v.w = (v.w - m.w) * r.w * g.w + b.w;
    ((float4*)h)[i] = v;
}

// ---------------- launch ----------------
extern "C" void kernel_launch(void* const* d_in, const int* in_sizes, int n_in,
                              void* d_out, int out_size) {
    const float* node_feats = (const float*)d_in[0];
    const void*  src        = d_in[1];               // int32 or int64, probed on device
    const void*  dst        = d_in[2];
    const float* eps        = (const float*)d_in[3];
    const float* W1         = (const float*)d_in[4];
    const float* b1         = (const float*)d_in[5];
    const float* W2         = (const float*)d_in[6];
    const float* b2         = (const float*)d_in[7];
    const float* gamma      = (const float*)d_in[8];
    const float* beta       = (const float*)d_in[9];
    float*       out        = (float*)d_out;

    const int n = in_sizes[0] / DIM;   // 100000
    const int E = in_sizes[1];         // 1600000

    // device-global scratch pointers
    float *h0, *h1, *colSum, *colSq, *mean, *rstd;
    int *counts, *offsets, *cursor, *edge_src, *blockSums, *is64;
    cudaGetSymbolAddress((void**)&h0, g_h0);
    cudaGetSymbolAddress((void**)&h1, g_h1);
    cudaGetSymbolAddress((void**)&counts, g_counts);
    cudaGetSymbolAddress((void**)&offsets, g_offsets);
    cudaGetSymbolAddress((void**)&cursor, g_cursor);
    cudaGetSymbolAddress((void**)&edge_src, g_edge_src);
    cudaGetSymbolAddress((void**)&blockSums, g_blockSums);
    cudaGetSymbolAddress((void**)&colSum, g_colSum);
    cudaGetSymbolAddress((void**)&colSq, g_colSq);
    cudaGetSymbolAddress((void**)&mean, g_mean);
    cudaGetSymbolAddress((void**)&rstd, g_rstd);
    cudaGetSymbolAddress((void**)&is64, g_is64);

    // 0) probe index dtype (int32 vs int64)
    detect_idx_kernel<<<1, 64>>>((const int*)dst, is64);

    // 1) zero counters + BN accumulators
    zero_int2<<<(n + 255) / 256, 256>>>(counts, n, cursor, n);
    zero_f2<<<(DIM + 255) / 256, 256>>>(colSum, colSq, DIM);

    // 2) CSR build
    hist_kernel<<<(E + 255) / 256, 256>>>(dst, counts, E, is64);
    int nb = (n + 1023) / 1024;
    scan_partial<<<nb, 1024>>>(counts, offsets, blockSums, n);
    scan_root<<<1, 32>>>(blockSums, nb);
    scan_add<<<nb, 1024>>>(offsets, blockSums, n);
    scatter_kernel<<<(E + 255) / 256, 256>>>(src, dst, offsets, cursor, edge_src, E, is64);

    // 3) aggregation: h0 = (1+eps)*x + segment_sum(x[src], dst)
    aggregate_kernel<<<n, 64>>>(node_feats, offsets, counts, edge_src, eps, h0, n);

    // 4) MLP layer 1: h1 = relu(h0 @ W1 + b1)   [n,256]x[256,512]
    {
        dim3 grid(DIM2 / 64, (n + 127) / 128);
        gemm_kernel<true><<<grid, 256>>>(h0, W1, b1, h1, n, DIM2, DIM);
    }
    // 5) MLP layer 2: out = h1 @ W2 + b2        [n,512]x[512,256]
    {
        dim3 grid(DIM / 64, (n + 127) / 128);
        gemm_kernel<false><<<grid, 256>>>(h1, W2, b2, out, n, DIM, DIM2);
    }

    // 6) BatchNorm (training mode, biased variance)
    bn_stats<<<512, DIM>>>(out, n, colSum, colSq);
    bn_final<<<1, DIM>>>(colSum, colSq, mean, rstd, n);
    int nvec = n * (DIM / 4);
    bn_apply<<<(nvec + 255) / 256, 256>>>(out, mean, rstd, gamma, beta, nvec);
}

// round 11
// speedup vs baseline: 1.9155x; 1.9155x over previous
#include <cuda_runtime.h>
#include <cuda_bf16.h>
#include <stdint.h>

// Problem constants (fixed by the dataset)
#define MAXN 100000
#define MAXE 1600000
#define DIM  256
#define DIM2 512
#define PADN (MAXN + 128)      // pad to M-tile multiple

// ---------------- scratch (no allocations allowed) ----------------
__device__ __nv_bfloat16 g_h0hi[(size_t)PADN * DIM];
__device__ __nv_bfloat16 g_h0lo[(size_t)PADN * DIM];
__device__ __nv_bfloat16 g_h1hi[(size_t)PADN * DIM2];
__device__ __nv_bfloat16 g_h1lo[(size_t)PADN * DIM2];
__device__ __nv_bfloat16 g_w1thi[(size_t)DIM2 * DIM];   // [N=512][K=256]
__device__ __nv_bfloat16 g_w1tlo[(size_t)DIM2 * DIM];
__device__ __nv_bfloat16 g_w2thi[(size_t)DIM * DIM2];   // [N=256][K=512]
__device__ __nv_bfloat16 g_w2tlo[(size_t)DIM * DIM2];
__device__ int   g_counts[MAXN];
__device__ int   g_offsets[MAXN];
__device__ int   g_cursor[MAXN];
__device__ int   g_edge_src[MAXE];
__device__ int   g_blockSums[256];
__device__ float g_colSum[DIM];
__device__ float g_colSq[DIM];
__device__ float g_mean[DIM];
__device__ float g_rstd[DIM];
__device__ int   g_is64;

// ---------------- dtype probe (int64 vs int32 indices) ----------------
__global__ void detect_idx_kernel(const int* __restrict__ dst_i32, int* __restrict__ is64) {
    __shared__ int any_nonzero;
    if (threadIdx.x == 0) any_nonzero = 0;
    __syncthreads();
    int v = dst_i32[2 * threadIdx.x + 1];
    if (v != 0) atomicOr(&any_nonzero, 1);
    __syncthreads();
    if (threadIdx.x == 0) *is64 = (any_nonzero == 0) ? 1 : 0;
}
__device__ __forceinline__ int load_idx(const void* p, int i, int is64) {
    if (is64) return (int)((const long long*)p)[i];
    return ((const int*)p)[i];
}

// ---------------- small utility kernels ----------------
__global__ void zero_int2(int* a, int n, int* b, int m) {
    int i = blockIdx.x * blockDim.x + threadIdx.x;
    if (i < n) a[i] = 0;
    if (i < m) b[i] = 0;
}
__global__ void zero_f2(float* a, float* b, int n) {
    int i = blockIdx.x * blockDim.x + threadIdx.x;
    if (i < n) { a[i] = 0.f; b[i] = 0.f; }
}

__global__ void hist_kernel(const void* __restrict__ dst, int* __restrict__ counts, int E,
                            const int* __restrict__ is64p) {
    int i = blockIdx.x * blockDim.x + threadIdx.x;
    if (i < E) atomicAdd(&counts[load_idx(dst, i, *is64p)], 1);
}

__global__ void scan_partial(const int* __restrict__ counts, int* __restrict__ offsets,
                             int* __restrict__ blockSums, int n) {
    __shared__ int sh[1024];
    int t = threadIdx.x;
    int i = blockIdx.x * 1024 + t;
    int v = (i < n) ? counts[i] : 0;
    sh[t] = v;
    __syncthreads();
    for (int off = 1; off < 1024; off <<= 1) {
        int x = (t >= off) ? sh[t - off] : 0;
        __syncthreads();
        sh[t] += x;
        __syncthreads();
    }
    if (i < n) offsets[i] = sh[t] - v;
    if (t == 1023) blockSums[blockIdx.x] = sh[t];
}
__global__ void scan_root(int* blockSums, int nb) {
    if (threadIdx.x == 0 && blockIdx.x == 0) {
        int run = 0;
        for (int i = 0; i < nb; i++) { int v = blockSums[i]; blockSums[i] = run; run += v; }
    }
}
__global__ void scan_add(int* __restrict__ offsets, const int* __restrict__ blockSums, int n) {
    int i = blockIdx.x * 1024 + threadIdx.x;
    if (i < n) offsets[i] += blockSums[blockIdx.x];
}
__global__ void scatter_kernel(const void* __restrict__ src, const void* __restrict__ dst,
                               const int* __restrict__ offsets, int* __restrict__ cursor,
                               int* __restrict__ edge_src, int E, const int* __restrict__ is64p) {
    int i = blockIdx.x * blockDim.x + threadIdx.x;
    if (i < E) {
        int is64 = *is64p;
        int d = load_idx(dst, i, is64);
        int s = load_idx(src, i, is64);
        int p = atomicAdd(&cursor[d], 1);
        edge_src[offsets[d] + p] = s;
    }
}

// gather-sum, emits bf16 hi/lo split directly
__global__ void aggregate_kernel(const float* __restrict__ nf,
                                 const int* __restrict__ offsets,
                                 const int* __restrict__ counts,
                                 const int* __restrict__ edge_src,
                                 const float* __restrict__ eps,
                                 __nv_bfloat16* __restrict__ h0hi,
                                 __nv_bfloat16* __restrict__ h0lo, int n) {
    int v = blockIdx.x;
    if (v >= n) return;
    int t = threadIdx.x;                         // 64 threads, one float4 each
    float s = 1.0f + eps[0];
    float4 a = *(const float4*)(nf + (size_t)v * DIM + t * 4);
    float4 acc = make_float4(a.x * s, a.y * s, a.z * s, a.w * s);
    int off = offsets[v];
    int deg = counts[v];
    int j = 0;
    for (; j + 4 <= deg; j += 4) {
        int u0 = edge_src[off + j + 0];
        int u1 = edge_src[off + j + 1];
        int u2 = edge_src[off + j + 2];
        int u3 = edge_src[off + j + 3];
        float4 b0 = *(const float4*)(nf + (size_t)u0 * DIM + t * 4);
        float4 b1 = *(const float4*)(nf + (size_t)u1 * DIM + t * 4);
        float4 b2 = *(const float4*)(nf + (size_t)u2 * DIM + t * 4);
        float4 b3 = *(const float4*)(nf + (size_t)u3 * DIM + t * 4);
        acc.x += b0.x + b1.x + b2.x + b3.x;
        acc.y += b0.y + b1.y + b2.y + b3.y;
        acc.z += b0.z + b1.z + b2.z + b3.z;
        acc.w += b0.w + b1.w + b2.w + b3.w;
    }
    for (; j < deg; j++) {
        int u = edge_src[off + j];
        float4 b = *(const float4*)(nf + (size_t)u * DIM + t * 4);
        acc.x += b.x; acc.y += b.y; acc.z += b.z; acc.w += b.w;
    }
    float vals[4] = {acc.x, acc.y, acc.z, acc.w};
    __nv_bfloat16 hi[4], lo[4];
#pragma unroll
    for (int c = 0; c < 4; c++) {
        hi[c] = __float2bfloat16(vals[c]);
        lo[c] = __float2bfloat16(vals[c] - __bfloat162float(hi[c]));
    }
    size_t base = (size_t)v * DIM + t * 4;
    *(__nv_bfloat162*)(h0hi + base)     = __nv_bfloat162(hi[0], hi[1]);
    *(__nv_bfloat162*)(h0hi + base + 2) = __nv_bfloat162(hi[2], hi[3]);
    *(__nv_bfloat162*)(h0lo + base)     = __nv_bfloat162(lo[0], lo[1]);
    *(__nv_bfloat162*)(h0lo + base + 2) = __nv_bfloat162(lo[2], lo[3]);
}

// weight transpose + bf16 split: W[K,N] row-major -> T[N,K] hi/lo
__global__ void wsplit_kernel(const float* __restrict__ W,
                              __nv_bfloat16* __restrict__ Thi,
                              __nv_bfloat16* __restrict__ Tlo, int K, int N) {
    int i = blockIdx.x * blockDim.x + threadIdx.x;
    if (i >= K * N) return;
    int k = i / N, n2 = i % N;
    float v = W[i];
    __nv_bfloat16 h = __float2bfloat16(v);
    Thi[(size_t)n2 * K + k] = h;
    Tlo[(size_t)n2 * K + k] = __float2bfloat16(v - __bfloat162float(h));
}

// ======================= mma.sync bf16 GEMM (no arch-'a' features) =======================
// C[M,N] = (Ahi+Alo)[M,K] @ (Bhi+Blo)[N,K]^T + bias; 3-term bf16 split, fp32 accum.
// BM=128, BN=128, BK=32, 256 threads (8 warps, 2x4), warp tile 64x32, 2-stage cp.async.

__device__ __forceinline__ uint32_t smem_to_u32(const void* p) {
    uint32_t a;
    asm("{ .reg .u64 t; cvta.to.shared.u64 t, %1; cvt.u32.u64 %0, t; }" : "=r"(a) : "l"(p));
    return a;
}
#define CP_ASYNC16(dst_u32, src_ptr) \
    asm volatile("cp.async.cg.shared.global [%0], [%1], 16;" :: "r"(dst_u32), "l"(src_ptr))
#define CP_COMMIT() asm volatile("cp.async.commit_group;" ::: "memory")
#define CP_WAIT1()  asm volatile("cp.async.wait_group 1;" ::: "memory")
#define CP_WAIT0()  asm volatile("cp.async.wait_group 0;" ::: "memory")

__device__ __forceinline__ void mma_bf16(float* c, const uint32_t* a, const uint32_t* b) {
    asm volatile("mma.sync.aligned.m16n8k16.row.col.f32.bf16.bf16.f32 "
                 "{%0,%1,%2,%3}, {%4,%5,%6,%7}, {%8,%9}, {%0,%1,%2,%3};"
                 : "+f"(c[0]), "+f"(c[1]), "+f"(c[2]), "+f"(c[3])
                 : "r"(a[0]), "r"(a[1]), "r"(a[2]), "r"(a[3]), "r"(b[0]), "r"(b[1]));
}

// SMEM layout: per stage 4 arrays of [128 rows][40 bf16] (stride 80B, conflict-free)
#define TSTRIDE  80                       // bytes per smem row (32 data + 8 pad bf16)
#define ARR_SZ   (128 * TSTRIDE)          // 10240 B
#define OFF_AHI  0
#define OFF_ALO  (ARR_SZ)
#define OFF_BHI  (2 * ARR_SZ)
#define OFF_BLO  (3 * ARR_SZ)
#define STAGE_SZ (4 * ARR_SZ)             // 40960 B
#define SMEM_TOT (2 * STAGE_SZ)           // 81920 B

template <bool SPLIT_OUT>
__global__ void __launch_bounds__(256, 1)
gemm_mma(const __nv_bfloat16* __restrict__ Ahi, const __nv_bfloat16* __restrict__ Alo,
         const __nv_bfloat16* __restrict__ Bhi, const __nv_bfloat16* __restrict__ Blo,
         const float* __restrict__ bias,
         float* __restrict__ Cf, __nv_bfloat16* __restrict__ Chi, __nv_bfloat16* __restrict__ Clo,
         int M, int N, int K) {
    extern __shared__ char smem[];
    const uint32_t sb = smem_to_u32(smem);
    const int tid = threadIdx.x;
    const int wid = tid >> 5;
    const int lane = tid & 31;
    const int warp_m = wid & 1;            // 2 warps over M (64 rows each)
    const int warp_n = wid >> 1;           // 4 warps over N (32 cols each)
    const int row0 = blockIdx.y * 128;
    const int col0 = blockIdx.x * 128;
    const int NC = K >> 5;                 // K-chunks of 32

    // global load indexing: id in [0,512): row r=id>>2, 16B-group g=id&3
    const int ldr = tid >> 1;              // 0..127 when paired with i*... (use id scheme below)

    float acc[4][4][4];
#pragma unroll
    for (int i = 0; i < 4; i++)
#pragma unroll
        for (int j = 0; j < 4; j++)
#pragma unroll
            for (int q = 0; q < 4; q++) acc[i][j][q] = 0.f;

    // ---- async load of one K-chunk into a stage ----
    auto load_chunk = [&](int kc, int stage) {
        const int kbase = kc * 32;
        const uint32_t s0 = sb + stage * STAGE_SZ;
#pragma unroll
        for (int i = 0; i < 2; i++) {
            int id = tid + i * 256;        // 0..511
            int r = id >> 2, g = id & 3;
            uint32_t so = (uint32_t)(r * TSTRIDE + g * 16);
            const size_t ga = (size_t)(row0 + r) * K + kbase + g * 8;
            const size_t gb = (size_t)(col0 + r) * K + kbase + g * 8;
            CP_ASYNC16(s0 + OFF_AHI + so, Ahi + ga);
            CP_ASYNC16(s0 + OFF_ALO + so, Alo + ga);
            CP_ASYNC16(s0 + OFF_BHI + so, Bhi + gb);
            CP_ASYNC16(s0 + OFF_BLO + so, Blo + gb);
        }
        CP_COMMIT();
    };

    load_chunk(0, 0);

    // fragment base offsets (bytes) within an array
    const uint32_t a_row = (uint32_t)(warp_m * 64 + (lane >> 2));
    const uint32_t a_base = a_row * TSTRIDE + (lane & 3) * 4;        // (r, k-pair)
    const uint32_t b_row = (uint32_t)(warp_n * 32 + (lane >> 2));
    const uint32_t b_base = b_row * TSTRIDE + (lane & 3) * 4;

    for (int kc = 0; kc < NC; kc++) {
        if (kc + 1 < NC) load_chunk(kc + 1, (kc + 1) & 1);
        if (kc + 1 < NC) { CP_WAIT1(); } else { CP_WAIT0(); }
        __syncthreads();

        const char* s0 = smem + (kc & 1) * STAGE_SZ;
#pragma unroll
        for (int ks = 0; ks < 2; ks++) {                  // two k16 steps per chunk
            const uint32_t koff = ks * 32;                // 16 bf16 = 32 B
            uint32_t ah[4][4], al[4][4], bh[4][2], bl[4][2];
#pragma unroll
            for (int i = 0; i < 4; i++) {
                uint32_t o0 = a_base + i * 16 * TSTRIDE + koff;
                ah[i][0] = *(const uint32_t*)(s0 + OFF_AHI + o0);
                ah[i][1] = *(const uint32_t*)(s0 + OFF_AHI + o0 + 8 * TSTRIDE);
                ah[i][2] = *(const uint32_t*)(s0 + OFF_AHI + o0 + 16);
                ah[i][3] = *(const uint32_t*)(s0 + OFF_AHI + o0 + 8 * TSTRIDE + 16);
                al[i][0] = *(const uint32_t*)(s0 + OFF_ALO + o0);
                al[i][1] = *(const uint32_t*)(s0 + OFF_ALO + o0 + 8 * TSTRIDE);
                al[i][2] = *(const uint32_t*)(s0 + OFF_ALO + o0 + 16);
                al[i][3] = *(const uint32_t*)(s0 + OFF_ALO + o0 + 8 * TSTRIDE + 16);
            }
#pragma unroll
            for (int j = 0; j < 4; j++) {
                uint32_t o0 = b_base + j * 8 * TSTRIDE + koff;
                bh[j][0] = *(const uint32_t*)(s0 + OFF_BHI + o0);
                bh[j][1] = *(const uint32_t*)(s0 + OFF_BHI + o0 + 16);
                bl[j][0] = *(const uint32_t*)(s0 + OFF_BLO + o0);
                bl[j][1] = *(const uint32_t*)(s0 + OFF_BLO + o0 + 16);
            }
#pragma unroll
            for (int i = 0; i < 4; i++)
#pragma unroll
                for (int j = 0; j < 4; j++) {
                    mma_bf16(acc[i][j], ah[i], bh[j]);    // hi*hi
                    mma_bf16(acc[i][j], ah[i], bl[j]);    // hi*lo
                    mma_bf16(acc[i][j], al[i], bh[j]);    // lo*hi
                }
        }
        __syncthreads();
    }

    // ---- epilogue ----
    const int rbase = row0 + warp_m * 64 + (lane >> 2);
    const int cbase = col0 + warp_n * 32 + (lane & 3) * 2;
#pragma unroll
    for (int i = 0; i < 4; i++) {
#pragma unroll
        for (int j = 0; j < 4; j++) {
            int c = cbase + j * 8;
            float bi0 = __ldg(bias + c);
            float bi1 = __ldg(bias + c + 1);
#pragma unroll
            for (int half = 0; half < 2; half++) {
                int r = rbase + i * 16 + half * 8;
                if (r >= M) continue;
                float v0 = acc[i][j][half * 2 + 0] + bi0;
                float v1 = acc[i][j][half * 2 + 1] + bi1;
                if (SPLIT_OUT) {
                    v0 = fmaxf(v0, 0.f);
                    v1 = fmaxf(v1, 0.f);
                    __nv_bfloat16 h0b = __float2bfloat16(v0);
                    __nv_bfloat16 h1b = __float2bfloat16(v1);
                    __nv_bfloat16 l0b = __float2bfloat16(v0 - __bfloat162float(h0b));
                    __nv_bfloat16 l1b = __float2bfloat16(v1 - __bfloat162float(h1b));
                    size_t o = (size_t)r * N + c;
                    *(__nv_bfloat162*)(Chi + o) = __nv_bfloat162(h0b, h1b);
                    *(__nv_bfloat162*)(Clo + o) = __nv_bfloat162(l0b, l1b);
                } else {
                    size_t o = (size_t)r * N + c;
                    Cf[o]     = v0;
                    Cf[o + 1] = v1;
                }
            }
        }
    }
}

// ---------------- BatchNorm ----------------
__global__ void bn_stats(const float* __restrict__ h, int M,
                         float* __restrict__ colSum, float* __restrict__ colSq) {
    int c = threadIdx.x;
    float s = 0.f, q = 0.f;
    for (int r = blockIdx.x; r < M; r += gridDim.x) {
        float v = h[(size_t)r * DIM + c];
        s += v; q += v * v;
    }
    atomicAdd(&colSum[c], s);
    atomicAdd(&colSq[c], q);
}
__global__ void bn_final(const float* __restrict__ colSum, const float* __restrict__ colSq,
                         float* __restrict__ mean, float* __restrict__ rstd, int M) {
    int c = threadIdx.x;
    float invM = 1.0f / (float)M;
    float m = colSum[c] * invM;
    float var = colSq[c] * invM - m * m;
    mean[c] = m;
    rstd[c] = rsqrtf(var + 1e-5f);
}
__global__ void bn_apply(float* __restrict__ h,
                         const float* __restrict__ mean, const float* __restrict__ rstd,
                         const float* __restrict__ gamma, const float* __restrict__ beta,
                         int nvec) {
    int i = blockIdx.x * blockDim.x + threadIdx.x;
    if (i >= nvec) return;
    int c4 = (i & 63) * 4;
    float4 v = ((float4*)h)[i];
    float4 m = *(const float4*)(mean + c4);
    float4 r = *(const float4*)(rstd + c4);
    float4 g = *(const float4*)(gamma + c4);
    float4 b = *(const float4*)(beta + c4);
    v.x = (v.x - m.x) * r.x * g.x + b.x;
    v.y = (v.y - m.y) * r.y * g.y + b.y;
    v.z = (v.z - m.z) * r.z * g.z + b.z;
    v.w = (v.w - m.w) * r.w * g.w + b.w;
    ((float4*)h)[i] = v;
}

// ---------------- launch ----------------
extern "C" void kernel_launch(void* const* d_in, const int* in_sizes, int n_in,
                              void* d_out, int out_size) {
    const float* node_feats = (const float*)d_in[0];
    const void*  src        = d_in[1];
    const void*  dst        = d_in[2];
    const float* eps        = (const float*)d_in[3];
    const float* W1         = (const float*)d_in[4];
    const float* b1         = (const float*)d_in[5];
    const float* W2         = (const float*)d_in[6];
    const float* b2         = (const float*)d_in[7];
    const float* gamma      = (const float*)d_in[8];
    const float* beta       = (const float*)d_in[9];
    float*       out        = (float*)d_out;

    const int n = in_sizes[0] / DIM;   // 100000
    const int E = in_sizes[1];         // 1600000

    __nv_bfloat16 *h0hi, *h0lo, *h1hi, *h1lo, *w1thi, *w1tlo, *w2thi, *w2tlo;
    float *colSum, *colSq, *mean, *rstd;
    int *counts, *offsets, *cursor, *edge_src, *blockSums, *is64;
    cudaGetSymbolAddress((void**)&h0hi, g_h0hi);
    cudaGetSymbolAddress((void**)&h0lo, g_h0lo);
    cudaGetSymbolAddress((void**)&h1hi, g_h1hi);
    cudaGetSymbolAddress((void**)&h1lo, g_h1lo);
    cudaGetSymbolAddress((void**)&w1thi, g_w1thi);
    cudaGetSymbolAddress((void**)&w1tlo, g_w1tlo);
    cudaGetSymbolAddress((void**)&w2thi, g_w2thi);
    cudaGetSymbolAddress((void**)&w2tlo, g_w2tlo);
    cudaGetSymbolAddress((void**)&counts, g_counts);
    cudaGetSymbolAddress((void**)&offsets, g_offsets);
    cudaGetSymbolAddress((void**)&cursor, g_cursor);
    cudaGetSymbolAddress((void**)&edge_src, g_edge_src);
    cudaGetSymbolAddress((void**)&blockSums, g_blockSums);
    cudaGetSymbolAddress((void**)&colSum, g_colSum);
    cudaGetSymbolAddress((void**)&colSq, g_colSq);
    cudaGetSymbolAddress((void**)&mean, g_mean);
    cudaGetSymbolAddress((void**)&rstd, g_rstd);
    cudaGetSymbolAddress((void**)&is64, g_is64);

    cudaFuncSetAttribute(gemm_mma<true>,  cudaFuncAttributeMaxDynamicSharedMemorySize, SMEM_TOT);
    cudaFuncSetAttribute(gemm_mma<false>, cudaFuncAttributeMaxDynamicSharedMemorySize, SMEM_TOT);

    // 0) probe index dtype + weight prep (transpose + bf16 split)
    detect_idx_kernel<<<1, 64>>>((const int*)dst, is64);
    wsplit_kernel<<<(DIM * DIM2 + 255) / 256, 256>>>(W1, w1thi, w1tlo, DIM, DIM2);
    wsplit_kernel<<<(DIM * DIM2 + 255) / 256, 256>>>(W2, w2thi, w2tlo, DIM2, DIM);

    // 1) zero counters + BN accumulators
    zero_int2<<<(n + 255) / 256, 256>>>(counts, n, cursor, n);
    zero_f2<<<(DIM + 255) / 256, 256>>>(colSum, colSq, DIM);

    // 2) CSR build
    hist_kernel<<<(E + 255) / 256, 256>>>(dst, counts, E, is64);
    int nb = (n + 1023) / 1024;
    scan_partial<<<nb, 1024>>>(counts, offsets, blockSums, n);
    scan_root<<<1, 32>>>(blockSums, nb);
    scan_add<<<nb, 1024>>>(offsets, blockSums, n);
    scatter_kernel<<<(E + 255) / 256, 256>>>(src, dst, offsets, cursor, edge_src, E, is64);

    // 3) aggregation -> bf16 hi/lo
    aggregate_kernel<<<n, 64>>>(node_feats, offsets, counts, edge_src, eps, h0hi, h0lo, n);

    // 4) MLP layer 1 (mma.sync): h1 = relu(h0 @ W1 + b1), bf16-split output
    const int MT = (n + 127) / 128;
    gemm_mma<true><<<dim3(DIM2 / 128, MT), 256, SMEM_TOT>>>(
        h0hi, h0lo, w1thi, w1tlo, b1, nullptr, h1hi, h1lo, n, DIM2, DIM);

    // 5) MLP layer 2 (mma.sync): out = h1 @ W2 + b2, fp32 output
    gemm_mma<false><<<dim3(DIM / 128, MT), 256, SMEM_TOT>>>(
        h1hi, h1lo, w2thi, w2tlo, b2, out, nullptr, nullptr, n, DIM, DIM2);

    // 6) BatchNorm (training mode, biased variance)
    bn_stats<<<512, DIM>>>(out, n, colSum, colSq);
    bn_final<<<1, DIM>>>(colSum, colSq, mean, rstd, n);
    int nvec = n * (DIM / 4);
    bn_apply<<<(nvec + 255) / 256, 256>>>(out, mean, rstd, gamma, beta, nvec);
}

// round 12
// speedup vs baseline: 1.9943x; 1.0411x over previous
#include <cuda_runtime.h>
#include <cuda_bf16.h>
#include <stdint.h>

// Problem constants (fixed by the dataset)
#define MAXN 100000
#define MAXE 1600000
#define DIM  256
#define DIM2 512
#define PADN (MAXN + 128)      // pad to M-tile multiple

// ---------------- scratch (no allocations allowed) ----------------
__device__ __nv_bfloat16 g_h0hi[(size_t)PADN * DIM];
__device__ __nv_bfloat16 g_h0lo[(size_t)PADN * DIM];
__device__ __nv_bfloat16 g_h1hi[(size_t)PADN * DIM2];
__device__ __nv_bfloat16 g_h1lo[(size_t)PADN * DIM2];
__device__ __nv_bfloat16 g_w1thi[(size_t)DIM2 * DIM];   // [N=512][K=256]
__device__ __nv_bfloat16 g_w1tlo[(size_t)DIM2 * DIM];
__device__ __nv_bfloat16 g_w2thi[(size_t)DIM * DIM2];   // [N=256][K=512]
__device__ __nv_bfloat16 g_w2tlo[(size_t)DIM * DIM2];
__device__ int   g_counts[MAXN];
__device__ int   g_offsets[MAXN];
__device__ int   g_cursor[MAXN];
__device__ int   g_edge_src[MAXE];
__device__ int   g_blockSums[256];
__device__ float g_colSum[DIM];
__device__ float g_colSq[DIM];
__device__ float g_mean[DIM];
__device__ float g_rstd[DIM];
__device__ int   g_is64;

// ---------------- dtype probe (int64 vs int32 indices) ----------------
__global__ void detect_idx_kernel(const int* __restrict__ dst_i32, int* __restrict__ is64) {
    __shared__ int any_nonzero;
    if (threadIdx.x == 0) any_nonzero = 0;
    __syncthreads();
    int v = dst_i32[2 * threadIdx.x + 1];
    if (v != 0) atomicOr(&any_nonzero, 1);
    __syncthreads();
    if (threadIdx.x == 0) *is64 = (any_nonzero == 0) ? 1 : 0;
}
__device__ __forceinline__ int load_idx(const void* p, int i, int is64) {
    if (is64) return (int)((const long long*)p)[i];
    return ((const int*)p)[i];
}

// ---------------- small utility kernels ----------------
__global__ void zero_all(int* a, int n, int* b, int m, float* f1, float* f2, int nf) {
    int i = blockIdx.x * blockDim.x + threadIdx.x;
    if (i < n) a[i] = 0;
    if (i < m) b[i] = 0;
    if (i < nf) { f1[i] = 0.f; f2[i] = 0.f; }
}

__global__ void hist_kernel(const void* __restrict__ dst, int* __restrict__ counts, int E,
                            const int* __restrict__ is64p) {
    int i = blockIdx.x * blockDim.x + threadIdx.x;
    if (i < E) atomicAdd(&counts[load_idx(dst, i, *is64p)], 1);
}

__global__ void scan_partial(const int* __restrict__ counts, int* __restrict__ offsets,
                             int* __restrict__ blockSums, int n) {
    __shared__ int sh[1024];
    int t = threadIdx.x;
    int i = blockIdx.x * 1024 + t;
    int v = (i < n) ? counts[i] : 0;
    sh[t] = v;
    __syncthreads();
    for (int off = 1; off < 1024; off <<= 1) {
        int x = (t >= off) ? sh[t - off] : 0;
        __syncthreads();
        sh[t] += x;
        __syncthreads();
    }
    if (i < n) offsets[i] = sh[t] - v;
    if (t == 1023) blockSums[blockIdx.x] = sh[t];
}
__global__ void scan_root(int* blockSums, int nb) {
    if (threadIdx.x == 0 && blockIdx.x == 0) {
        int run = 0;
        for (int i = 0; i < nb; i++) { int v = blockSums[i]; blockSums[i] = run; run += v; }
    }
}
__global__ void scan_add(int* __restrict__ offsets, const int* __restrict__ blockSums, int n) {
    int i = blockIdx.x * 1024 + threadIdx.x;
    if (i < n) offsets[i] += blockSums[blockIdx.x];
}
__global__ void scatter_kernel(const void* __restrict__ src, const void* __restrict__ dst,
                               const int* __restrict__ offsets, int* __restrict__ cursor,
                               int* __restrict__ edge_src, int E, const int* __restrict__ is64p) {
    int i = blockIdx.x * blockDim.x + threadIdx.x;
    if (i < E) {
        int is64 = *is64p;
        int d = load_idx(dst, i, is64);
        int s = load_idx(src, i, is64);
        int p = atomicAdd(&cursor[d], 1);
        edge_src[offsets[d] + p] = s;
    }
}

// gather-sum, emits bf16 hi/lo split directly
__global__ void aggregate_kernel(const float* __restrict__ nf,
                                 const int* __restrict__ offsets,
                                 const int* __restrict__ counts,
                                 const int* __restrict__ edge_src,
                                 const float* __restrict__ eps,
                                 __nv_bfloat16* __restrict__ h0hi,
                                 __nv_bfloat16* __restrict__ h0lo, int n) {
    int v = blockIdx.x;
    if (v >= n) return;
    int t = threadIdx.x;                         // 64 threads, one float4 each
    float s = 1.0f + eps[0];
    float4 a = *(const float4*)(nf + (size_t)v * DIM + t * 4);
    float4 acc = make_float4(a.x * s, a.y * s, a.z * s, a.w * s);
    int off = offsets[v];
    int deg = counts[v];
    int j = 0;
    for (; j + 8 <= deg; j += 8) {               // batch 8 rows for MLP
        float4 b[8];
#pragma unroll
        for (int q = 0; q < 8; q++) {
            int u = edge_src[off + j + q];
            b[q] = *(const float4*)(nf + (size_t)u * DIM + t * 4);
        }
#pragma unroll
        for (int q = 0; q < 8; q++) {
            acc.x += b[q].x; acc.y += b[q].y; acc.z += b[q].z; acc.w += b[q].w;
        }
    }
    for (; j < deg; j++) {
        int u = edge_src[off + j];
        float4 b = *(const float4*)(nf + (size_t)u * DIM + t * 4);
        acc.x += b.x; acc.y += b.y; acc.z += b.z; acc.w += b.w;
    }
    float vals[4] = {acc.x, acc.y, acc.z, acc.w};
    __nv_bfloat16 hi[4], lo[4];
#pragma unroll
    for (int c = 0; c < 4; c++) {
        hi[c] = __float2bfloat16(vals[c]);
        lo[c] = __float2bfloat16(vals[c] - __bfloat162float(hi[c]));
    }
    size_t base = (size_t)v * DIM + t * 4;
    *(__nv_bfloat162*)(h0hi + base)     = __nv_bfloat162(hi[0], hi[1]);
    *(__nv_bfloat162*)(h0hi + base + 2) = __nv_bfloat162(hi[2], hi[3]);
    *(__nv_bfloat162*)(h0lo + base)     = __nv_bfloat162(lo[0], lo[1]);
    *(__nv_bfloat162*)(h0lo + base + 2) = __nv_bfloat162(lo[2], lo[3]);
}

// weight transpose + bf16 split: W[K,N] row-major -> T[N,K] hi/lo
__global__ void wsplit_kernel(const float* __restrict__ W,
                              __nv_bfloat16* __restrict__ Thi,
                              __nv_bfloat16* __restrict__ Tlo, int K, int N) {
    int i = blockIdx.x * blockDim.x + threadIdx.x;
    if (i >= K * N) return;
    int k = i / N, n2 = i % N;
    float v = W[i];
    __nv_bfloat16 h = __float2bfloat16(v);
    Thi[(size_t)n2 * K + k] = h;
    Tlo[(size_t)n2 * K + k] = __float2bfloat16(v - __bfloat162float(h));
}

// ======================= mma.sync bf16 GEMM + ldmatrix =======================
// C[M,N] = (Ahi+Alo)[M,K] @ (Bhi+Blo)[N,K]^T + bias; 3-term bf16 split, fp32 accum.
// BM=128, BN=128, BK=32, 256 threads (8 warps, 2x4), warp tile 64x32, 2-stage cp.async.

__device__ __forceinline__ uint32_t smem_to_u32(const void* p) {
    uint32_t a;
    asm("{ .reg .u64 t; cvta.to.shared.u64 t, %1; cvt.u32.u64 %0, t; }" : "=r"(a) : "l"(p));
    return a;
}
#define CP_ASYNC16(dst_u32, src_ptr) \
    asm volatile("cp.async.cg.shared.global [%0], [%1], 16;" :: "r"(dst_u32), "l"(src_ptr))
#define CP_COMMIT() asm volatile("cp.async.commit_group;" ::: "memory")
#define CP_WAIT1()  asm volatile("cp.async.wait_group 1;" ::: "memory")
#define CP_WAIT0()  asm volatile("cp.async.wait_group 0;" ::: "memory")

__device__ __forceinline__ void mma_bf16(float* c, const uint32_t* a, const uint32_t* b) {
    asm volatile("mma.sync.aligned.m16n8k16.row.col.f32.bf16.bf16.f32 "
                 "{%0,%1,%2,%3}, {%4,%5,%6,%7}, {%8,%9}, {%0,%1,%2,%3};"
                 : "+f"(c[0]), "+f"(c[1]), "+f"(c[2]), "+f"(c[3])
                 : "r"(a[0]), "r"(a[1]), "r"(a[2]), "r"(a[3]), "r"(b[0]), "r"(b[1]));
}
__device__ __forceinline__ void ldmx4(uint32_t* r, uint32_t addr) {
    asm volatile("ldmatrix.sync.aligned.m8n8.x4.shared.b16 {%0,%1,%2,%3}, [%4];"
                 : "=r"(r[0]), "=r"(r[1]), "=r"(r[2]), "=r"(r[3]) : "r"(addr));
}

// SMEM layout: per stage 4 arrays of [128 rows][40 bf16] (stride 80B, conflict-free)
#define TSTRIDE  80                       // bytes per smem row (32 data + 8 pad bf16)
#define ARR_SZ   (128 * TSTRIDE)          // 10240 B
#define OFF_AHI  0
#define OFF_ALO  (ARR_SZ)
#define OFF_BHI  (2 * ARR_SZ)
#define OFF_BLO  (3 * ARR_SZ)
#define STAGE_SZ (4 * ARR_SZ)             // 40960 B
#define SMEM_TOT (2 * STAGE_SZ)           // 81920 B

template <bool SPLIT_OUT>
__global__ void __launch_bounds__(256, 1)
gemm_mma(const __nv_bfloat16* __restrict__ Ahi, const __nv_bfloat16* __restrict__ Alo,
         const __nv_bfloat16* __restrict__ Bhi, const __nv_bfloat16* __restrict__ Blo,
         const float* __restrict__ bias,
         float* __restrict__ Cf, __nv_bfloat16* __restrict__ Chi, __nv_bfloat16* __restrict__ Clo,
         int M, int N, int K) {
    extern __shared__ char smem[];
    const uint32_t sb = smem_to_u32(smem);
    const int tid = threadIdx.x;
    const int wid = tid >> 5;
    const int lane = tid & 31;
    const int warp_m = wid & 1;            // 2 warps over M (64 rows each)
    const int warp_n = wid >> 1;           // 4 warps over N (32 cols each)
    const int row0 = blockIdx.y * 128;
    const int col0 = blockIdx.x * 128;
    const int NC = K >> 5;                 // K-chunks of 32

    float acc[4][4][4];
#pragma unroll
    for (int i = 0; i < 4; i++)
#pragma unroll
        for (int j = 0; j < 4; j++)
#pragma unroll
            for (int q = 0; q < 4; q++) acc[i][j][q] = 0.f;

    // ---- async load of one K-chunk into a stage ----
    auto load_chunk = [&](int kc, int stage) {
        const int kbase = kc * 32;
        const uint32_t s0 = sb + stage * STAGE_SZ;
#pragma unroll
        for (int i = 0; i < 2; i++) {
            int id = tid + i * 256;        // 0..511
            int r = id >> 2, g = id & 3;
            uint32_t so = (uint32_t)(r * TSTRIDE + g * 16);
            const size_t ga = (size_t)(row0 + r) * K + kbase + g * 8;
            const size_t gb = (size_t)(col0 + r) * K + kbase + g * 8;
            CP_ASYNC16(s0 + OFF_AHI + so, Ahi + ga);
            CP_ASYNC16(s0 + OFF_ALO + so, Alo + ga);
            CP_ASYNC16(s0 + OFF_BHI + so, Bhi + gb);
            CP_ASYNC16(s0 + OFF_BLO + so, Blo + gb);
        }
        CP_COMMIT();
    };

    load_chunk(0, 0);

    // ldmatrix lane-address bases (within an array, stage 0)
    // A (m16k16 x4): lanes 0-15 -> rows 0-15, lanes 16-31 -> +16B col offset
    const uint32_t a_lm = (uint32_t)((warp_m * 64 + (lane & 15)) * TSTRIDE + (lane >> 4) * 16);
    // B (two n8k16 per x4): lanes 0-7 n0-7/k0, 8-15 n0-7/k8, 16-23 n8-15/k0, 24-31 n8-15/k8
    const uint32_t b_lm = (uint32_t)((warp_n * 32 + (lane & 7) + ((lane >> 4) << 3)) * TSTRIDE
                                     + ((lane >> 3) & 1) * 16);

    for (int kc = 0; kc < NC; kc++) {
        if (kc + 1 < NC) load_chunk(kc + 1, (kc + 1) & 1);
        if (kc + 1 < NC) { CP_WAIT1(); } else { CP_WAIT0(); }
        __syncthreads();

        const uint32_t s0 = sb + (kc & 1) * STAGE_SZ;
#pragma unroll
        for (int ks = 0; ks < 2; ks++) {                  // two k16 steps per chunk
            const uint32_t koff = ks * 32;                // 16 bf16 = 32 B
            uint32_t ah[4][4], al[4][4], bh[4][2], bl[4][2];
#pragma unroll
            for (int i = 0; i < 4; i++) {
                uint32_t ao = a_lm + i * 16 * TSTRIDE + koff;
                ldmx4(ah[i], s0 + OFF_AHI + ao);
                ldmx4(al[i], s0 + OFF_ALO + ao);
            }
#pragma unroll
            for (int p = 0; p < 2; p++) {                 // each x4 covers 2 j's
                uint32_t bo = b_lm + p * 16 * TSTRIDE + koff;
                uint32_t rh[4], rl[4];
                ldmx4(rh, s0 + OFF_BHI + bo);
                ldmx4(rl, s0 + OFF_BLO + bo);
                bh[2 * p][0] = rh[0]; bh[2 * p][1] = rh[1];
                bh[2 * p + 1][0] = rh[2]; bh[2 * p + 1][1] = rh[3];
                bl[2 * p][0] = rl[0]; bl[2 * p][1] = rl[1];
                bl[2 * p + 1][0] = rl[2]; bl[2 * p + 1][1] = rl[3];
            }
#pragma unroll
            for (int i = 0; i < 4; i++)
#pragma unroll
                for (int j = 0; j < 4; j++) {
                    mma_bf16(acc[i][j], ah[i], bh[j]);    // hi*hi
                    mma_bf16(acc[i][j], ah[i], bl[j]);    // hi*lo
                    mma_bf16(acc[i][j], al[i], bh[j]);    // lo*hi
                }
        }
        __syncthreads();
    }

    // ---- epilogue ----
    const int rbase = row0 + warp_m * 64 + (lane >> 2);
    const int cbase = col0 + warp_n * 32 + (lane & 3) * 2;
#pragma unroll
    for (int i = 0; i < 4; i++) {
#pragma unroll
        for (int j = 0; j < 4; j++) {
            int c = cbase + j * 8;
            float bi0 = __ldg(bias + c);
            float bi1 = __ldg(bias + c + 1);
#pragma unroll
            for (int half = 0; half < 2; half++) {
                int r = rbase + i * 16 + half * 8;
                if (r >= M) continue;
                float v0 = acc[i][j][half * 2 + 0] + bi0;
                float v1 = acc[i][j][half * 2 + 1] + bi1;
                if (SPLIT_OUT) {
                    v0 = fmaxf(v0, 0.f);
                    v1 = fmaxf(v1, 0.f);
                    __nv_bfloat16 h0b = __float2bfloat16(v0);
                    __nv_bfloat16 h1b = __float2bfloat16(v1);
                    __nv_bfloat16 l0b = __float2bfloat16(v0 - __bfloat162float(h0b));
                    __nv_bfloat16 l1b = __float2bfloat16(v1 - __bfloat162float(h1b));
                    size_t o = (size_t)r * N + c;
                    *(__nv_bfloat162*)(Chi + o) = __nv_bfloat162(h0b, h1b);
                    *(__nv_bfloat162*)(Clo + o) = __nv_bfloat162(l0b, l1b);
                } else {
                    *(float2*)(Cf + (size_t)r * N + c) = make_float2(v0, v1);
                }
            }
        }
    }
}

// ---------------- BatchNorm ----------------
__global__ void bn_stats(const float* __restrict__ h, int M,
                         float* __restrict__ colSum, float* __restrict__ colSq) {
    int c = threadIdx.x;
    float s = 0.f, q = 0.f;
    for (int r = blockIdx.x; r < M; r += gridDim.x) {
        float v = h[(size_t)r * DIM + c];
        s += v; q += v * v;
    }
    atomicAdd(&colSum[c], s);
    atomicAdd(&colSq[c], q);
}
__global__ void bn_final(const float* __restrict__ colSum, const float* __restrict__ colSq,
                         float* __restrict__ mean, float* __restrict__ rstd, int M) {
    int c = threadIdx.x;
    float invM = 1.0f / (float)M;
    float m = colSum[c] * invM;
    float var = colSq[c] * invM - m * m;
    mean[c] = m;
    rstd[c] = rsqrtf(var + 1e-5f);
}
__global__ void bn_apply(float* __restrict__ h,
                         const float* __restrict__ mean, const float* __restrict__ rstd,
                         const float* __restrict__ gamma, const float* __restrict__ beta,
                         int nvec) {
    int i = blockIdx.x * blockDim.x + threadIdx.x;
    if (i >= nvec) return;
    int c4 = (i & 63) * 4;
    float4 v = ((float4*)h)[i];
    float4 m = *(const float4*)(mean + c4);
    float4 r = *(const float4*)(rstd + c4);
    float4 g = *(const float4*)(gamma + c4);
    float4 b = *(const float4*)(beta + c4);
    v.x = (v.x - m.x) * r.x * g.x + b.x;
    v.y = (v.y - m.y) * r.y * g.y + b.y;
    v.z = (v.z - m.z) * r.z * g.z + b.z;
    v.w = (v.w - m.w) * r.w * g.w + b.w;
    ((float4*)h)[i] = v;
}

// ---------------- launch ----------------
extern "C" void kernel_launch(void* const* d_in, const int* in_sizes, int n_in,
                              void* d_out, int out_size) {
    const float* node_feats = (const float*)d_in[0];
    const void*  src        = d_in[1];
    const void*  dst        = d_in[2];
    const float* eps        = (const float*)d_in[3];
    const float* W1         = (const float*)d_in[4];
    const float* b1         = (const float*)d_in[5];
    const float* W2         = (const float*)d_in[6];
    const float* b2         = (const float*)d_in[7];
    const float* gamma      = (const float*)d_in[8];
    const float* beta       = (const float*)d_in[9];
    float*       out        = (float*)d_out;

    const int n = in_sizes[0] / DIM;   // 100000
    const int E = in_sizes[1];         // 1600000

    __nv_bfloat16 *h0hi, *h0lo, *h1hi, *h1lo, *w1thi, *w1tlo, *w2thi, *w2tlo;
    float *colSum, *colSq, *mean, *rstd;
    int *counts, *offsets, *cursor, *edge_src, *blockSums, *is64;
    cudaGetSymbolAddress((void**)&h0hi, g_h0hi);
    cudaGetSymbolAddress((void**)&h0lo, g_h0lo);
    cudaGetSymbolAddress((void**)&h1hi, g_h1hi);
    cudaGetSymbolAddress((void**)&h1lo, g_h1lo);
    cudaGetSymbolAddress((void**)&w1thi, g_w1thi);
    cudaGetSymbolAddress((void**)&w1tlo, g_w1tlo);
    cudaGetSymbolAddress((void**)&w2thi, g_w2thi);
    cudaGetSymbolAddress((void**)&w2tlo, g_w2tlo);
    cudaGetSymbolAddress((void**)&counts, g_counts);
    cudaGetSymbolAddress((void**)&offsets, g_offsets);
    cudaGetSymbolAddress((void**)&cursor, g_cursor);
    cudaGetSymbolAddress((void**)&edge_src, g_edge_src);
    cudaGetSymbolAddress((void**)&blockSums, g_blockSums);
    cudaGetSymbolAddress((void**)&colSum, g_colSum);
    cudaGetSymbolAddress((void**)&colSq, g_colSq);
    cudaGetSymbolAddress((void**)&mean, g_mean);
    cudaGetSymbolAddress((void**)&rstd, g_rstd);
    cudaGetSymbolAddress((void**)&is64, g_is64);

    cudaFuncSetAttribute(gemm_mma<true>,  cudaFuncAttributeMaxDynamicSharedMemorySize, SMEM_TOT);
    cudaFuncSetAttribute(gemm_mma<false>, cudaFuncAttributeMaxDynamicSharedMemorySize, SMEM_TOT);

    // 0) probe index dtype + weight prep (transpose + bf16 split)
    detect_idx_kernel<<<1, 64>>>((const int*)dst, is64);
    wsplit_kernel<<<(DIM * DIM2 + 255) / 256, 256>>>(W1, w1thi, w1tlo, DIM, DIM2);
    wsplit_kernel<<<(DIM * DIM2 + 255) / 256, 256>>>(W2, w2thi, w2tlo, DIM2, DIM);

    // 1) zero counters + BN accumulators
    zero_all<<<(n + 255) / 256, 256>>>(counts, n, cursor, n, colSum, colSq, DIM);

    // 2) CSR build
    hist_kernel<<<(E + 255) / 256, 256>>>(dst, counts, E, is64);
    int nb = (n + 1023) / 1024;
    scan_partial<<<nb, 1024>>>(counts, offsets, blockSums, n);
    scan_root<<<1, 32>>>(blockSums, nb);
    scan_add<<<nb, 1024>>>(offsets, blockSums, n);
    scatter_kernel<<<(E + 255) / 256, 256>>>(src, dst, offsets, cursor, edge_src, E, is64);

    // 3) aggregation -> bf16 hi/lo
    aggregate_kernel<<<n, 64>>>(node_feats, offsets, counts, edge_src, eps, h0hi, h0lo, n);

    // 4) MLP layer 1 (mma.sync + ldmatrix): h1 = relu(h0 @ W1 + b1), bf16-split output
    const int MT = (n + 127) / 128;
    gemm_mma<true><<<dim3(DIM2 / 128, MT), 256, SMEM_TOT>>>(
        h0hi, h0lo, w1thi, w1tlo, b1, nullptr, h1hi, h1lo, n, DIM2, DIM);

    // 5) MLP layer 2 (mma.sync + ldmatrix): out = h1 @ W2 + b2, fp32 output
    gemm_mma<false><<<dim3(DIM / 128, MT), 256, SMEM_TOT>>>(
        h1hi, h1lo, w2thi, w2tlo, b2, out, nullptr, nullptr, n, DIM, DIM2);

    // 6) BatchNorm (training mode, biased variance)
    bn_stats<<<512, DIM>>>(out, n, colSum, colSq);
    bn_final<<<1, DIM>>>(colSum, colSq, mean, rstd, n);
    int nvec = n * (DIM / 4);
    bn_apply<<<(nvec + 255) / 256, 256>>>(out, mean, rstd, gamma, beta, nvec);
}